// round 14
// baseline (speedup 1.0000x reference)
#include <cuda_runtime.h>
#include <math.h>

#define GRID_H   48
#define NPTS     2304
#define NCH      16
#define NOFF     277       // in-circle window offsets (dr^2+dc^2 <= 88)
#define MAXE     64        // per-warp compacted list capacity (~35 + pipeline pad)
#define XSTRIDE  36864     // NPTS*NCH

// Phase A + spline + compaction, warp-local. Round 0 full; round 1 has nvl lanes.
__device__ __forceinline__ int phase_a(
    int lane, int nvl2, float inv_h, int ri, int ci, float xi, float yi,
    const int* __restrict__ drv, const int* __restrict__ dcv,
    const float* __restrict__ distv, const int* __restrict__ joffv,
    const float4* __restrict__ wva, const float* __restrict__ sS,
    float b2, int ibase, float2* __restrict__ wjRow)
{
    const float inv47 = 1.0f / 47.0f;
    float xj[2], yj[2], acc[2];
#pragma unroll
    for (int r = 0; r < 2; r++) {
        xj[r] = fmaf((float)drv[r], inv47, xi);
        yj[r] = fmaf((float)dcv[r], inv47, yi);
        acc[r] = 0.0f;
    }
#pragma unroll
    for (int k = 0; k < 32; k++) {
        float4 w = wva[k];    // LDS.128 broadcast
#pragma unroll
        for (int r = 0; r < 2; r++) {
            float t = fmaf(yj[r], w.y, fmaf(xj[r], w.x, w.w));
            acc[r] = fmaf(w.z, fmaxf(t, 0.0f), acc[r]);
        }
    }
    const float CKNOT = 1.0f / (1.0f / 15.0f + 1e-8f);
    int cnt = 0;
#pragma unroll
    for (int r = 0; r < 2; r++) {
        int rj = ri + drv[r];
        int cj = ci + dcv[r];
        bool ok = ((unsigned)rj < GRID_H) && ((unsigned)cj < GRID_H);
        if (r == 1) ok = ok && (lane < nvl2);
        unsigned m = __ballot_sync(0xffffffffu, ok);
        if (ok) {
            float rr  = fminf(distv[r] * inv_h, 1.0f);
            int   idx = min((int)(rr * 15.0f), 14);
            float wr  = (rr - (float)idx * (1.0f / 15.0f)) * CKNOT;
            float s0  = sS[idx];
            float psi = fmaf(wr, sS[idx + 1] - s0, s0);
            float w   = (acc[r] + b2) * psi;
            int  pos  = cnt + __popc(m & ((1u << lane) - 1u));
            wjRow[pos] = make_float2(w, __int_as_float(ibase + joffv[r]));
        }
        cnt += __popc(m);
    }
    return cnt;
}

__global__ __launch_bounds__(256, 5)
void si_blocks_kernel(const float* __restrict__ x,
                      const float* __restrict__ phi_w1, const float* __restrict__ phi_b1,
                      const float* __restrict__ phi_w2, const float* __restrict__ phi_b2,
                      const float* __restrict__ h_w1,  const float* __restrict__ h_b1,
                      const float* __restrict__ h_w2,  const float* __restrict__ h_b2,
                      const float* __restrict__ S_m,
                      float* __restrict__ out)
{
    __shared__ float  sS[16], sDist[89];
    __shared__ int    sOff[288];                 // packed (dr+9)<<5 | (dc+9)
    __shared__ float  sInvH;
    __shared__ float4 sWVA[8][32];               // per-warp (w2,w3,v,a) rows
    __shared__ float2 sWJ[8][MAXE];              // per-warp compacted lists
    __shared__ int    sCnt[8];
    __shared__ float4 sPart[8][8];

    const int tid  = threadIdx.x;
    const int sub  = tid >> 5;     // 8 warps per i
    const int lane = tid & 31;
    const float inv47 = 1.0f / 47.0f;

    const int   i  = blockIdx.x;
    const int   ri = i / GRID_H;
    const int   ci = i - ri * GRID_H;
    const float xi = (float)ri * inv47;
    const float yi = (float)ci * inv47;

    // ---- block init (warps specialize) ----
    if (tid < 16) sS[tid] = S_m[tid];
    for (int l = tid; l < 89; l += 256) sDist[l] = sqrtf((float)l) * inv47;
    if (sub == 7) {   // compact in-circle offsets (deterministic order)
        int cnt = 0;
        for (int rr = 0; rr < 12; rr++) {
            int cand = lane + rr * 32;
            int q = cand / 19;
            int dr = q - 9, dc = cand - q * 19 - 9;
            bool ok = (cand < 361) && (dr * dr + dc * dc <= 88);
            unsigned m = __ballot_sync(0xffffffffu, ok);
            if (ok) sOff[cnt + __popc(m & ((1u << lane) - 1u))] = ((dr + 9) << 5) | (dc + 9);
            cnt += __popc(m);
        }
    }
    if (sub == 2) {   // h_net bandwidth, computed once per block
        float hz = fmaxf(fmaf(xi, __ldg(h_w1 + lane),
                         fmaf(yi, __ldg(h_w1 + 32 + lane), __ldg(h_b1 + lane))), 0.0f)
                   * __ldg(h_w2 + lane);
#pragma unroll
        for (int o = 16; o; o >>= 1) hz += __shfl_xor_sync(0xffffffffu, hz, o);
        hz += __ldg(h_b2);
        float e    = __expf(-fabsf(hz));
        float hval = fmaxf(hz, 0.0f) + __logf(1.0f + e);
        if (lane == 0) sInvH = __fdividef(1.0f, hval + 1e-6f);
    }

    // per-lane weights straight from gmem (L1-hot across 2304 blocks)
    const float w2L = __ldg(phi_w1 + 64 + lane);
    const float w3L = __ldg(phi_w1 + 96 + lane);
    const float vL  = __ldg(phi_w2 + lane);
    const float b2v = __ldg(phi_b2);

    // per-i phi row: (w2,w3,v,a) for k = lane, one STS.128
    float aL = fmaf(xi, __ldg(phi_w1 + lane),
               fmaf(yi, __ldg(phi_w1 + 32 + lane), __ldg(phi_b1 + lane)));
    sWVA[sub][lane] = make_float4(w2L, w3L, vL, aL);
    __syncthreads();   // sOff/sDist/sS/sInvH ready

    const float inv_h = sInvH;

    // ---- per-warp window geometry: round0 = sub*32+lane; round1 = 256+sub*3+lane ----
    const int nvl2 = (sub < 7) ? 3 : 0;
    int   drv[2], dcv[2], joffv[2];
    float distv[2];
#pragma unroll
    for (int r = 0; r < 2; r++) {
        int slot = (r == 0) ? (sub * 32 + lane) : min(256 + sub * 3 + lane, NOFF - 1);
        int pk = sOff[slot];
        int dr = (pk >> 5) - 9, dc = (pk & 31) - 9;
        drv[r] = dr; dcv[r] = dc;
        distv[r] = sDist[dr * dr + dc * dc];
        joffv[r] = (dr * GRID_H + dc) * NCH;
    }

    // ---- Phase A + compact ----
    float2* wjRow = sWJ[sub];
    int cnt = phase_a(lane, nvl2, inv_h, ri, ci, xi, yi, drv, dcv, distv, joffv,
                      sWVA[sub], sS, b2v, i * NCH, wjRow);
    if (lane < 24) wjRow[cnt + lane] = make_float2(0.0f, __int_as_float(0));
    if (lane == 0) sCnt[sub] = cnt;
    __syncwarp();

    // ---- Phase B: 8 slots x 2 batches x 16 ch per iter, fully pipelined ----
    const int n2 = lane >> 3;
    const int bb = (lane >> 2) & 1;
    const int qq = lane & 3;
    const float* xq = x + bb * XSTRIDE + qq * 4;
    const int cnt8 = (cnt + 7) & ~7;
    float4 acc = make_float4(0.f, 0.f, 0.f, 0.f);
    float2 wj0  = wjRow[n2];
    float2 wj1  = wjRow[4 + n2];
    float2 wjp0 = wjRow[8 + n2];
    float2 wjp1 = wjRow[12 + n2];
    float4 v0 = *reinterpret_cast<const float4*>(xq + __float_as_int(wj0.y));
    float4 v1 = *reinterpret_cast<const float4*>(xq + __float_as_int(wj1.y));
    for (int t = 0; t < cnt8; t += 8) {
        float2 wjq0 = wjRow[t + 16 + n2];
        float2 wjq1 = wjRow[t + 20 + n2];
        float4 vp0 = *reinterpret_cast<const float4*>(xq + __float_as_int(wjp0.y));
        float4 vp1 = *reinterpret_cast<const float4*>(xq + __float_as_int(wjp1.y));
        acc.x = fmaf(wj0.x, v0.x, acc.x);
        acc.y = fmaf(wj0.x, v0.y, acc.y);
        acc.z = fmaf(wj0.x, v0.z, acc.z);
        acc.w = fmaf(wj0.x, v0.w, acc.w);
        acc.x = fmaf(wj1.x, v1.x, acc.x);
        acc.y = fmaf(wj1.x, v1.y, acc.y);
        acc.z = fmaf(wj1.x, v1.z, acc.z);
        acc.w = fmaf(wj1.x, v1.w, acc.w);
        wj0 = wjp0; wj1 = wjp1;
        wjp0 = wjq0; wjp1 = wjq1;
        v0 = vp0; v1 = vp1;
    }
#pragma unroll
    for (int o = 8; o <= 16; o <<= 1) {
        acc.x += __shfl_xor_sync(0xffffffffu, acc.x, o);
        acc.y += __shfl_xor_sync(0xffffffffu, acc.y, o);
        acc.z += __shfl_xor_sync(0xffffffffu, acc.z, o);
        acc.w += __shfl_xor_sync(0xffffffffu, acc.w, o);
    }
    if (lane < 8) sPart[sub][lane] = acc;
    __syncthreads();

    if (sub == 0 && lane < 8) {
        float4 o = make_float4(0.f, 0.f, 0.f, 0.f);
        int tot = 0;
#pragma unroll
        for (int wsub = 0; wsub < 8; wsub++) {
            float4 s = sPart[wsub][lane];
            o.x += s.x; o.y += s.y; o.z += s.z; o.w += s.w;
            tot += sCnt[wsub];
        }
        float sc = __fdividef(1.0f, (float)tot);
        o.x *= sc; o.y *= sc; o.z *= sc; o.w *= sc;
        *reinterpret_cast<float4*>(out + bb * XSTRIDE + i * NCH + qq * 4) = o;
    }
}

extern "C" void kernel_launch(void* const* d_in, const int* in_sizes, int n_in,
                              void* d_out, int out_size)
{
    const float* x      = (const float*)d_in[0];
    const float* phi_w1 = (const float*)d_in[1];
    const float* phi_b1 = (const float*)d_in[2];
    const float* phi_w2 = (const float*)d_in[3];
    const float* phi_b2 = (const float*)d_in[4];
    const float* h_w1   = (const float*)d_in[5];
    const float* h_b1   = (const float*)d_in[6];
    const float* h_w2   = (const float*)d_in[7];
    const float* h_b2   = (const float*)d_in[8];
    const float* S_m    = (const float*)d_in[9];
    float* out = (float*)d_out;

    si_blocks_kernel<<<NPTS, 256>>>(
        x, phi_w1, phi_b1, phi_w2, phi_b2,
        h_w1, h_b1, h_w2, h_b2, S_m, out);
}

// round 15
// speedup vs baseline: 1.2284x; 1.2284x over previous
#include <cuda_runtime.h>
#include <math.h>

#define GRID_H   48
#define NPTS     2304
#define NCH      16
#define NOFF     277       // in-circle window offsets (dr^2+dc^2 <= 88)
#define MAXE     168       // 139 max valid + 24 pad + margin
#define XSTRIDE  36864     // NPTS*NCH
#define NRW      5         // rounds per warp (covers 139/138-slot halves)

__global__ __launch_bounds__(128, 8)
void si_blocks_kernel(const float* __restrict__ x,
                      const float* __restrict__ phi_w1, const float* __restrict__ phi_b1,
                      const float* __restrict__ phi_w2, const float* __restrict__ phi_b2,
                      const float* __restrict__ h_w1,  const float* __restrict__ h_b1,
                      const float* __restrict__ h_w2,  const float* __restrict__ h_b2,
                      const float* __restrict__ S_m,
                      float* __restrict__ out)
{
    __shared__ float  sS[16];
    __shared__ float  sInvH[2];
    __shared__ int2   sG[280];                  // {pk, dist_bits} per in-circle slot
    __shared__ float4 sWVA[2][32];              // per-i (w2,w3,v,a) rows
    __shared__ float2 sWJ[4][MAXE];             // per-warp compacted lists
    __shared__ int    sCnt[4];
    __shared__ float4 sPart[2][8];

    const int tid  = threadIdx.x;
    const int warp = tid >> 5;
    const int lane = tid & 31;
    const int p    = warp >> 1;    // which i in block
    const int sub  = warp & 1;     // which half of candidate set
    const float inv47 = 1.0f / 47.0f;

    const int   i  = blockIdx.x * 2 + p;
    const int   ri = i / GRID_H;
    const int   ci = i - ri * GRID_H;
    const float xi = (float)ri * inv47;
    const float yi = (float)ci * inv47;

    // ---- block init: warps specialize ----
    if (tid < 16) sS[tid] = S_m[tid];
    if (warp == 3) {   // compact in-circle offsets + dist (deterministic order)
        int cnt = 0;
        for (int rr = 0; rr < 12; rr++) {
            int cand = lane + rr * 32;
            int q = cand / 19;
            int dr = q - 9, dc = cand - q * 19 - 9;
            int id2 = dr * dr + dc * dc;
            bool ok = (cand < 361) && (id2 <= 88);
            unsigned m = __ballot_sync(0xffffffffu, ok);
            if (ok) {
                int pos = cnt + __popc(m & ((1u << lane) - 1u));
                sG[pos] = make_int2(((dr + 9) << 5) | (dc + 9),
                                    __float_as_int(sqrtf((float)id2) * inv47));
            }
            cnt += __popc(m);
        }
    }
    if (sub == 0) {    // warps 0,2: h_net for own i + weight row for own i
        float hz = fmaxf(fmaf(xi, __ldg(h_w1 + lane),
                         fmaf(yi, __ldg(h_w1 + 32 + lane), __ldg(h_b1 + lane))), 0.0f)
                   * __ldg(h_w2 + lane);
#pragma unroll
        for (int o = 16; o; o >>= 1) hz += __shfl_xor_sync(0xffffffffu, hz, o);
        hz += __ldg(h_b2);
        float e    = __expf(-fabsf(hz));
        float hval = fmaxf(hz, 0.0f) + __logf(1.0f + e);
        if (lane == 0) sInvH[p] = __fdividef(1.0f, hval + 1e-6f);

        float aL = fmaf(xi, __ldg(phi_w1 + lane),
                   fmaf(yi, __ldg(phi_w1 + 32 + lane), __ldg(phi_b1 + lane)));
        sWVA[p][lane] = make_float4(__ldg(phi_w1 + 64 + lane),
                                    __ldg(phi_w1 + 96 + lane),
                                    __ldg(phi_w2 + lane), aL);
    }
    const float b2v = __ldg(phi_b2);
    __syncthreads();

    const float inv_h = sInvH[p];

    // ---- per-warp geometry: contiguous halves 0..138 / 139..276, 5 rounds ----
    const int base = sub ? 139 : 0;
    const int nvl  = sub ? 10 : 11;     // valid lanes in last round
    float xj[NRW], yj[NRW], distv[NRW];
    int   joffv[NRW];
    unsigned okbits = 0;
#pragma unroll
    for (int r = 0; r < NRW; r++) {
        int slot = min(base + 32 * r + lane, NOFF - 1);
        int2 g = sG[slot];
        int dr = (g.x >> 5) - 9, dc = (g.x & 31) - 9;
        int rj = ri + dr, cj = ci + dc;
        bool ok = ((unsigned)rj < GRID_H) && ((unsigned)cj < GRID_H);
        if (r == NRW - 1) ok = ok && (lane < nvl);
        if (ok) okbits |= (1u << r);
        xj[r] = fmaf((float)dr, inv47, xi);
        yj[r] = fmaf((float)dc, inv47, yi);
        distv[r] = __int_as_float(g.y);
        joffv[r] = i * NCH + (dr * GRID_H + dc) * NCH;
    }

    // ---- Phase A: phi hidden layer, 5 candidates per lane ----
    const float4* wva = sWVA[p];
    float acc[NRW];
#pragma unroll
    for (int r = 0; r < NRW; r++) acc[r] = 0.0f;
#pragma unroll
    for (int k = 0; k < 32; k++) {
        float4 w = wva[k];    // LDS.128 broadcast
#pragma unroll
        for (int r = 0; r < NRW; r++) {
            float t = fmaf(yj[r], w.y, fmaf(xj[r], w.x, w.w));
            acc[r] = fmaf(w.z, fmaxf(t, 0.0f), acc[r]);
        }
    }

    // ---- spline + mask + compaction ----
    const float CKNOT = 1.0f / (1.0f / 15.0f + 1e-8f);
    float2* wjRow = sWJ[warp];
    int cnt = 0;
#pragma unroll
    for (int r = 0; r < NRW; r++) {
        bool ok = (okbits >> r) & 1;
        unsigned m = __ballot_sync(0xffffffffu, ok);
        if (ok) {
            float rr  = fminf(distv[r] * inv_h, 1.0f);
            int   idx = min((int)(rr * 15.0f), 14);
            float wr  = (rr - (float)idx * (1.0f / 15.0f)) * CKNOT;
            float s0  = sS[idx];
            float psi = fmaf(wr, sS[idx + 1] - s0, s0);
            float w   = (acc[r] + b2v) * psi;
            int  pos  = cnt + __popc(m & ((1u << lane) - 1u));
            wjRow[pos] = make_float2(w, __int_as_float(joffv[r]));
        }
        cnt += __popc(m);
    }
    if (lane < 24) wjRow[cnt + lane] = make_float2(0.0f, __int_as_float(0));
    if (lane == 0) sCnt[warp] = cnt;
    __syncwarp();

    // ---- Phase B: 8 slots x 2 batches x 16 ch per iter, fully pipelined ----
    const int n2 = lane >> 3;
    const int bb = (lane >> 2) & 1;
    const int qq = lane & 3;
    const float* xq = x + bb * XSTRIDE + qq * 4;
    const int cnt8 = (cnt + 7) & ~7;
    float4 acc4 = make_float4(0.f, 0.f, 0.f, 0.f);
    float2 wj0  = wjRow[n2];
    float2 wj1  = wjRow[4 + n2];
    float2 wjp0 = wjRow[8 + n2];
    float2 wjp1 = wjRow[12 + n2];
    float4 v0 = *reinterpret_cast<const float4*>(xq + __float_as_int(wj0.y));
    float4 v1 = *reinterpret_cast<const float4*>(xq + __float_as_int(wj1.y));
    for (int t = 0; t < cnt8; t += 8) {
        float2 wjq0 = wjRow[t + 16 + n2];
        float2 wjq1 = wjRow[t + 20 + n2];
        float4 vp0 = *reinterpret_cast<const float4*>(xq + __float_as_int(wjp0.y));
        float4 vp1 = *reinterpret_cast<const float4*>(xq + __float_as_int(wjp1.y));
        acc4.x = fmaf(wj0.x, v0.x, acc4.x);
        acc4.y = fmaf(wj0.x, v0.y, acc4.y);
        acc4.z = fmaf(wj0.x, v0.z, acc4.z);
        acc4.w = fmaf(wj0.x, v0.w, acc4.w);
        acc4.x = fmaf(wj1.x, v1.x, acc4.x);
        acc4.y = fmaf(wj1.x, v1.y, acc4.y);
        acc4.z = fmaf(wj1.x, v1.z, acc4.z);
        acc4.w = fmaf(wj1.x, v1.w, acc4.w);
        wj0 = wjp0; wj1 = wjp1;
        wjp0 = wjq0; wjp1 = wjq1;
        v0 = vp0; v1 = vp1;
    }
#pragma unroll
    for (int o = 8; o <= 16; o <<= 1) {
        acc4.x += __shfl_xor_sync(0xffffffffu, acc4.x, o);
        acc4.y += __shfl_xor_sync(0xffffffffu, acc4.y, o);
        acc4.z += __shfl_xor_sync(0xffffffffu, acc4.z, o);
        acc4.w += __shfl_xor_sync(0xffffffffu, acc4.w, o);
    }
    if (sub == 1 && lane < 8) sPart[p][lane] = acc4;

    // sync only the 2 warps of this i
    asm volatile("bar.sync %0, 64;" :: "r"(p + 1) : "memory");

    if (sub == 0 && lane < 8) {
        float4 s1 = sPart[p][lane];
        int tot = sCnt[2 * p] + sCnt[2 * p + 1];
        float sc = __fdividef(1.0f, (float)tot);
        float4 o;
        o.x = (acc4.x + s1.x) * sc;
        o.y = (acc4.y + s1.y) * sc;
        o.z = (acc4.z + s1.z) * sc;
        o.w = (acc4.w + s1.w) * sc;
        *reinterpret_cast<float4*>(out + bb * XSTRIDE + i * NCH + qq * 4) = o;
    }
}

extern "C" void kernel_launch(void* const* d_in, const int* in_sizes, int n_in,
                              void* d_out, int out_size)
{
    const float* x      = (const float*)d_in[0];
    const float* phi_w1 = (const float*)d_in[1];
    const float* phi_b1 = (const float*)d_in[2];
    const float* phi_w2 = (const float*)d_in[3];
    const float* phi_b2 = (const float*)d_in[4];
    const float* h_w1   = (const float*)d_in[5];
    const float* h_b1   = (const float*)d_in[6];
    const float* h_w2   = (const float*)d_in[7];
    const float* h_b2   = (const float*)d_in[8];
    const float* S_m    = (const float*)d_in[9];
    float* out = (float*)d_out;

    si_blocks_kernel<<<NPTS / 2, 128>>>(
        x, phi_w1, phi_b1, phi_w2, phi_b2,
        h_w1, h_b1, h_w2, h_b2, S_m, out);
}